// round 2
// baseline (speedup 1.0000x reference)
#include <cuda_runtime.h>
#include <cstdint>

// Shifted-window attention: B=32, W=8192, C=64, ws=64, shift=32.
// 4096 windows, one CTA each. fp32 with packed f32x2 FMA.

#define TPB 256
#define NBLK 4096

// smem float offsets
#define SM_A 0        // Qt (gemm1), then Pt (gemm2)  [d][p] swizzled
#define SM_K 4096     // Kt [d][c] swizzled
#define SM_V 8192     // V  [m][c] row-major
#define SM_T 12288    // bias table (127 floats)
#define SM_FLOATS (12288 + 128)

__device__ __forceinline__ unsigned long long pk2(float x) {
    unsigned long long r;
    asm("mov.b64 %0, {%1, %1};" : "=l"(r) : "f"(x));
    return r;
}
__device__ __forceinline__ float2 unpk(unsigned long long v) {
    float2 r;
    asm("mov.b64 {%0, %1}, %2;" : "=f"(r.x), "=f"(r.y) : "l"(v));
    return r;
}
#define FMA2(acc, a, b) asm("fma.rn.f32x2 %0, %1, %2, %0;" : "+l"(acc) : "l"(a), "l"(b))

extern "C" __global__ void __launch_bounds__(TPB, 3)
win_attn_kernel(const float* __restrict__ q, const float* __restrict__ k,
                const float* __restrict__ v, const float* __restrict__ tab,
                float* __restrict__ out)
{
    extern __shared__ float sm[];
    const int tid = threadIdx.x;
    const int g   = blockIdx.x;
    const int bb  = g >> 7;          // batch
    const int w   = g & 127;         // window within batch
    const int start = w * 64 + 32;   // cyclic shift by -32 handled as gather
    const long batch_base = (long)bb * 8192;

    // ---- load q,k,v window; q,k transposed+swizzled, v row-major ----
    #pragma unroll
    for (int it = 0; it < 4; ++it) {
        int idx = it * 256 + tid;
        int p   = idx >> 4;          // window position 0..63
        int c4  = idx & 15;          // float4 chunk along head dim
        int row = (start + p) & 8191;
        long go = (batch_base + row) * 64 + c4 * 4;
        float4 qv = *(const float4*)(q + go);
        float4 kv = *(const float4*)(k + go);
        float4 vv = *(const float4*)(v + go);
        *(float4*)&sm[SM_V + p * 64 + c4 * 4] = vv;
        float qa[4] = {qv.x, qv.y, qv.z, qv.w};
        float ka[4] = {kv.x, kv.y, kv.z, kv.w};
        #pragma unroll
        for (int e = 0; e < 4; ++e) {
            int d = c4 * 4 + e;
            int off = d * 64 + ((((p >> 2) ^ (d & 15) ^ (d >> 4)) & 15) << 2) + (p & 3);
            sm[SM_A + off] = qa[e];
            sm[SM_K + off] = ka[e];
        }
    }
    if (tid < 127) sm[SM_T + tid] = tab[tid];
    __syncthreads();

    const int tx = tid & 15, ty = tid >> 4;
    const int c0 = tx * 4, r0 = ty * 4;

    // ---- gemm1: S = Q K^T (rows r0..r0+3, cols c0..c0+3) ----
    unsigned long long acc[8];   // acc[i*2+j2]: row r0+i, col pair (c0+2j2, +1)
    #pragma unroll
    for (int i = 0; i < 8; ++i) acc[i] = 0ull;

    #pragma unroll
    for (int d = 0; d < 64; ++d) {
        int sw = (d & 15) ^ (d >> 4);
        float4 a4 = *(const float4*)&sm[SM_A + d * 64 + (((ty ^ sw) & 15) << 2)];
        ulonglong2 b2 = *(const ulonglong2*)&sm[SM_K + d * 64 + (((tx ^ sw) & 15) << 2)];
        unsigned long long a0 = pk2(a4.x), a1 = pk2(a4.y), a2 = pk2(a4.z), a3 = pk2(a4.w);
        FMA2(acc[0], a0, b2.x); FMA2(acc[1], a0, b2.y);
        FMA2(acc[2], a1, b2.x); FMA2(acc[3], a1, b2.y);
        FMA2(acc[4], a2, b2.x); FMA2(acc[5], a2, b2.y);
        FMA2(acc[6], a3, b2.x); FMA2(acc[7], a3, b2.y);
    }

    // ---- epilogue: scale + bias + mask, softmax ----
    float s[4][4];
    #pragma unroll
    for (int i = 0; i < 4; ++i) {
        float2 u0 = unpk(acc[i * 2 + 0]);
        float2 u1 = unpk(acc[i * 2 + 1]);
        s[i][0] = u0.x; s[i][1] = u0.y; s[i][2] = u1.x; s[i][3] = u1.y;
    }
    float t7[7];
    {
        int tb0 = r0 - c0 + 60;   // bias(i,j) = table[(r0+i)-(c0+j)+63] = t7[i-j+3]
        #pragma unroll
        for (int z = 0; z < 7; ++z) t7[z] = sm[SM_T + tb0 + z];
    }
    const float mk = (w == 127 && ((r0 < 32) != (c0 < 32))) ? -100.0f : 0.0f;
    #pragma unroll
    for (int i = 0; i < 4; ++i)
        #pragma unroll
        for (int j = 0; j < 4; ++j)
            s[i][j] = s[i][j] * 0.125f + t7[i - j + 3] + mk;

    float mx[4], sum[4];
    #pragma unroll
    for (int i = 0; i < 4; ++i) {
        float m = fmaxf(fmaxf(s[i][0], s[i][1]), fmaxf(s[i][2], s[i][3]));
        m = fmaxf(m, __shfl_xor_sync(0xffffffffu, m, 1));
        m = fmaxf(m, __shfl_xor_sync(0xffffffffu, m, 2));
        m = fmaxf(m, __shfl_xor_sync(0xffffffffu, m, 4));
        m = fmaxf(m, __shfl_xor_sync(0xffffffffu, m, 8));
        mx[i] = m;
        #pragma unroll
        for (int j = 0; j < 4; ++j) s[i][j] = __expf(s[i][j] - m);
        float r = s[i][0] + s[i][1] + s[i][2] + s[i][3];
        r += __shfl_xor_sync(0xffffffffu, r, 1);
        r += __shfl_xor_sync(0xffffffffu, r, 2);
        r += __shfl_xor_sync(0xffffffffu, r, 4);
        r += __shfl_xor_sync(0xffffffffu, r, 8);
        sum[i] = r;
        float inv = __fdividef(1.0f, r);
        #pragma unroll
        for (int j = 0; j < 4; ++j) s[i][j] *= inv;
    }
    (void)mx; (void)sum;

    // ---- write attn directly from registers (coalesced STG.128) ----
    {
        float* oat = out + (long)32 * 8192 * 64 + (long)g * 4096;
        #pragma unroll
        for (int i = 0; i < 4; ++i)
            *(float4*)(oat + (r0 + i) * 64 + c0) = make_float4(s[i][0], s[i][1], s[i][2], s[i][3]);
    }

    __syncthreads();   // everyone done reading Qt before Pt overwrites SM_A
    // store P transposed+swizzled: Pt[m][r]
    #pragma unroll
    for (int j = 0; j < 4; ++j) {
        int m = c0 + j;
        int off = m * 64 + (((ty ^ (m & 15) ^ (m >> 4)) & 15) << 2);
        *(float4*)&sm[SM_A + off] = make_float4(s[0][j], s[1][j], s[2][j], s[3][j]);
    }
    __syncthreads();

    // ---- gemm2: O = P V ----
    #pragma unroll
    for (int i = 0; i < 8; ++i) acc[i] = 0ull;
    #pragma unroll
    for (int m = 0; m < 64; ++m) {
        int sw = (m & 15) ^ (m >> 4);
        float4 a4 = *(const float4*)&sm[SM_A + m * 64 + (((ty ^ sw) & 15) << 2)];
        ulonglong2 b2 = *(const ulonglong2*)&sm[SM_V + m * 64 + c0];
        unsigned long long a0 = pk2(a4.x), a1 = pk2(a4.y), a2 = pk2(a4.z), a3 = pk2(a4.w);
        FMA2(acc[0], a0, b2.x); FMA2(acc[1], a0, b2.y);
        FMA2(acc[2], a1, b2.x); FMA2(acc[3], a1, b2.y);
        FMA2(acc[4], a2, b2.x); FMA2(acc[5], a2, b2.y);
        FMA2(acc[6], a3, b2.x); FMA2(acc[7], a3, b2.y);
    }

    // ---- write x with inverse cyclic shift (scatter) ----
    #pragma unroll
    for (int i = 0; i < 4; ++i) {
        float2 u0 = unpk(acc[i * 2 + 0]);
        float2 u1 = unpk(acc[i * 2 + 1]);
        int row = (start + r0 + i) & 8191;
        *(float4*)(out + (batch_base + row) * 64 + c0) = make_float4(u0.x, u0.y, u1.x, u1.y);
    }
}

extern "C" void kernel_launch(void* const* d_in, const int* in_sizes, int n_in,
                              void* d_out, int out_size)
{
    const float* q   = (const float*)d_in[0];
    const float* k   = (const float*)d_in[1];
    const float* v   = (const float*)d_in[2];
    const float* tab = (const float*)d_in[3];
    float* out = (float*)d_out;
    (void)in_sizes; (void)n_in; (void)out_size;

    size_t smem = SM_FLOATS * sizeof(float);   // 49664 B > 48K default
    cudaFuncSetAttribute(win_attn_kernel,
                         cudaFuncAttributeMaxDynamicSharedMemorySize, (int)smem);
    win_attn_kernel<<<NBLK, TPB, smem>>>(q, k, v, tab, out);
}

// round 3
// speedup vs baseline: 1.0938x; 1.0938x over previous
#include <cuda_runtime.h>
#include <cstdint>

// Shifted-window attention: B=32, W=8192, C=64, ws=64, shift=32.
// 4096 windows, one CTA (64 threads) each, 8x8 output tile per thread,
// packed f32x2 FMA. FMA2-pipe-bound design (~113K chip cycles ideal).

#define TPB 64
#define NBLK 4096

// smem float offsets (all arrays: row*64 + swizzled-slot layout)
#define SM_A 0        // Qt (gemm1) then Pt (gemm2): [d][r]
#define SM_K 4096     // Kt: [d][c]
#define SM_V 8192     // V : [m][c]
#define SM_T 12288    // bias table (127 floats)
#define SM_FLOATS (12288 + 128)

__device__ __forceinline__ unsigned long long pk2(float x) {
    unsigned long long r;
    asm("mov.b64 %0, {%1, %1};" : "=l"(r) : "f"(x));
    return r;
}
__device__ __forceinline__ float2 unpk(unsigned long long v) {
    float2 r;
    asm("mov.b64 {%0, %1}, %2;" : "=f"(r.x), "=f"(r.y) : "l"(v));
    return r;
}
#define FMA2(acc, a, b) asm("fma.rn.f32x2 %0, %1, %2, %0;" : "+l"(acc) : "l"(a), "l"(b))

extern "C" __global__ void __launch_bounds__(TPB, 4)
win_attn_kernel(const float* __restrict__ q, const float* __restrict__ k,
                const float* __restrict__ v, const float* __restrict__ tab,
                float* __restrict__ out)
{
    extern __shared__ float sm[];
    const int tid = threadIdx.x;
    const int g   = blockIdx.x;
    const int bb  = g >> 7;          // batch
    const int w   = g & 127;         // window within batch
    const int start = w * 64 + 32;   // cyclic shift by -32 handled as gather
    const long batch_base = (long)bb * 8192;

    // ---- load q,k,v window ----
    // Qt/Kt transposed: row=d, col=p.  V: row=p, col=c.
    // swizzle: element (row,c) -> row*64 + ((c>>2 + row>>2)&15)*4 + (c&3)
    #pragma unroll 4
    for (int it = 0; it < 16; ++it) {
        int idx = it * TPB + tid;    // 0..1023
        int p   = idx >> 4;          // window position 0..63
        int c4  = idx & 15;          // float4 chunk along head dim
        int row = (start + p) & 8191;
        long go = (batch_base + row) * 64 + c4 * 4;
        float4 qv = *(const float4*)(q + go);
        float4 kv = *(const float4*)(k + go);
        float4 vv = *(const float4*)(v + go);
        int p4 = p >> 2;
        *(float4*)&sm[SM_V + p * 64 + (((c4 + p4) & 15) << 2)] = vv;
        // Qt/Kt rows d = 4*c4+e, col p; slot = (p>>2 + d>>2)&15, d>>2 == c4
        int off = (4 * c4) * 64 + (((p4 + c4) & 15) << 2) + (p & 3);
        float qa[4] = {qv.x, qv.y, qv.z, qv.w};
        float ka[4] = {kv.x, kv.y, kv.z, kv.w};
        #pragma unroll
        for (int e = 0; e < 4; ++e) {
            sm[SM_A + off + e * 64] = qa[e];
            sm[SM_K + off + e * 64] = ka[e];
        }
    }
    for (int i = tid; i < 127; i += TPB) sm[SM_T + i] = tab[i];
    __syncthreads();

    const int tx = tid & 7, ty = tid >> 3;   // tx: col group, ty: row group
    // thread owns rows ty*8..+7, cols {4tx..4tx+3, 4tx+32..4tx+35}

    unsigned long long acc[32];   // acc[i*4+pp]: row i, col-pairs of the 8 cols
    #pragma unroll
    for (int i = 0; i < 32; ++i) acc[i] = 0ull;

    // ---- gemm1: S = Q K^T ----
    for (int d4 = 0; d4 < 16; ++d4) {
        int sa1 = ((2 * ty + d4) & 15) << 2;
        int sa2 = ((2 * ty + 1 + d4) & 15) << 2;
        int sb1 = ((tx + d4) & 15) << 2;
        int sb2 = ((tx + 8 + d4) & 15) << 2;
        const float* bA = sm + SM_A + d4 * 256;
        const float* bK = sm + SM_K + d4 * 256;
        #pragma unroll
        for (int e = 0; e < 4; ++e) {
            float4 a1 = *(const float4*)(bA + e * 64 + sa1);
            float4 a2 = *(const float4*)(bA + e * 64 + sa2);
            ulonglong2 b1 = *(const ulonglong2*)(bK + e * 64 + sb1);
            ulonglong2 b2 = *(const ulonglong2*)(bK + e * 64 + sb2);
            unsigned long long A[8] = {pk2(a1.x), pk2(a1.y), pk2(a1.z), pk2(a1.w),
                                       pk2(a2.x), pk2(a2.y), pk2(a2.z), pk2(a2.w)};
            #pragma unroll
            for (int i = 0; i < 8; ++i) {
                FMA2(acc[i * 4 + 0], A[i], b1.x);
                FMA2(acc[i * 4 + 1], A[i], b1.y);
                FMA2(acc[i * 4 + 2], A[i], b2.x);
                FMA2(acc[i * 4 + 3], A[i], b2.y);
            }
        }
    }

    // ---- epilogue: scale + bias + mask, softmax ----
    float s[8][8];
    #pragma unroll
    for (int i = 0; i < 8; ++i) {
        #pragma unroll
        for (int pp = 0; pp < 4; ++pp) {
            float2 u = unpk(acc[i * 4 + pp]);
            s[i][pp * 2] = u.x; s[i][pp * 2 + 1] = u.y;
        }
    }
    // window 127: block-diag mask between first/last 32 positions
    const float mkA = (w == 127 && ty >= 4) ? -100.0f : 0.0f;  // cols < 32
    const float mkB = (w == 127 && ty <  4) ? -100.0f : 0.0f;  // cols >= 32
    #pragma unroll
    for (int i = 0; i < 8; ++i) {
        int rbase = ty * 8 + i - 4 * tx + 63;   // r - 4tx + 63
        #pragma unroll
        for (int j = 0; j < 8; ++j) {
            int coff = (j & 3) + ((j >> 2) << 5);
            s[i][j] = s[i][j] * 0.125f + sm[SM_T + rbase - coff] + ((j < 4) ? mkA : mkB);
        }
        float m = s[i][0];
        #pragma unroll
        for (int j = 1; j < 8; ++j) m = fmaxf(m, s[i][j]);
        m = fmaxf(m, __shfl_xor_sync(0xffffffffu, m, 1));
        m = fmaxf(m, __shfl_xor_sync(0xffffffffu, m, 2));
        m = fmaxf(m, __shfl_xor_sync(0xffffffffu, m, 4));
        float r = 0.0f;
        #pragma unroll
        for (int j = 0; j < 8; ++j) { s[i][j] = __expf(s[i][j] - m); r += s[i][j]; }
        r += __shfl_xor_sync(0xffffffffu, r, 1);
        r += __shfl_xor_sync(0xffffffffu, r, 2);
        r += __shfl_xor_sync(0xffffffffu, r, 4);
        float inv = __fdividef(1.0f, r);
        #pragma unroll
        for (int j = 0; j < 8; ++j) s[i][j] *= inv;
    }

    // ---- write attn (fully coalesced: tx-contiguous 128B segments) ----
    {
        float* oat = out + (long)32 * 8192 * 64 + (long)g * 4096;
        #pragma unroll
        for (int i = 0; i < 8; ++i) {
            float* rp = oat + (ty * 8 + i) * 64;
            *(float4*)(rp + 4 * tx)      = make_float4(s[i][0], s[i][1], s[i][2], s[i][3]);
            *(float4*)(rp + 4 * tx + 32) = make_float4(s[i][4], s[i][5], s[i][6], s[i][7]);
        }
    }

    __syncthreads();   // all reads of Qt done before Pt overwrites SM_A
    // ---- store P transposed: Pt[m][r] (same swizzle) ----
    #pragma unroll
    for (int grp = 0; grp < 2; ++grp) {
        #pragma unroll
        for (int jj = 0; jj < 4; ++jj) {
            int m  = 4 * tx + 32 * grp + jj;
            int rm = tx + 8 * grp;          // m>>2
            int j  = grp * 4 + jj;
            float* bp = sm + SM_A + m * 64;
            *(float4*)(bp + (((2 * ty + rm) & 15) << 2)) =
                make_float4(s[0][j], s[1][j], s[2][j], s[3][j]);
            *(float4*)(bp + (((2 * ty + 1 + rm) & 15) << 2)) =
                make_float4(s[4][j], s[5][j], s[6][j], s[7][j]);
        }
    }
    __syncthreads();

    // ---- gemm2: O = P V ----
    #pragma unroll
    for (int i = 0; i < 32; ++i) acc[i] = 0ull;
    for (int d4 = 0; d4 < 16; ++d4) {
        int sa1 = ((2 * ty + d4) & 15) << 2;
        int sa2 = ((2 * ty + 1 + d4) & 15) << 2;
        int sb1 = ((tx + d4) & 15) << 2;
        int sb2 = ((tx + 8 + d4) & 15) << 2;
        const float* bA = sm + SM_A + d4 * 256;
        const float* bV = sm + SM_V + d4 * 256;
        #pragma unroll
        for (int e = 0; e < 4; ++e) {
            float4 a1 = *(const float4*)(bA + e * 64 + sa1);
            float4 a2 = *(const float4*)(bA + e * 64 + sa2);
            ulonglong2 b1 = *(const ulonglong2*)(bV + e * 64 + sb1);
            ulonglong2 b2 = *(const ulonglong2*)(bV + e * 64 + sb2);
            unsigned long long A[8] = {pk2(a1.x), pk2(a1.y), pk2(a1.z), pk2(a1.w),
                                       pk2(a2.x), pk2(a2.y), pk2(a2.z), pk2(a2.w)};
            #pragma unroll
            for (int i = 0; i < 8; ++i) {
                FMA2(acc[i * 4 + 0], A[i], b1.x);
                FMA2(acc[i * 4 + 1], A[i], b1.y);
                FMA2(acc[i * 4 + 2], A[i], b2.x);
                FMA2(acc[i * 4 + 3], A[i], b2.y);
            }
        }
    }

    // ---- write x with inverse cyclic shift (coalesced per row-group) ----
    #pragma unroll
    for (int i = 0; i < 8; ++i) {
        int row = (start + ty * 8 + i) & 8191;
        float* op = out + (batch_base + row) * 64;
        float2 u0 = unpk(acc[i * 4 + 0]);
        float2 u1 = unpk(acc[i * 4 + 1]);
        *(float4*)(op + 4 * tx) = make_float4(u0.x, u0.y, u1.x, u1.y);
        float2 u2 = unpk(acc[i * 4 + 2]);
        float2 u3 = unpk(acc[i * 4 + 3]);
        *(float4*)(op + 4 * tx + 32) = make_float4(u2.x, u2.y, u3.x, u3.y);
    }
}

extern "C" void kernel_launch(void* const* d_in, const int* in_sizes, int n_in,
                              void* d_out, int out_size)
{
    const float* q   = (const float*)d_in[0];
    const float* k   = (const float*)d_in[1];
    const float* v   = (const float*)d_in[2];
    const float* tab = (const float*)d_in[3];
    float* out = (float*)d_out;
    (void)in_sizes; (void)n_in; (void)out_size;

    size_t smem = SM_FLOATS * sizeof(float);   // 49664 B
    cudaFuncSetAttribute(win_attn_kernel,
                         cudaFuncAttributeMaxDynamicSharedMemorySize, (int)smem);
    win_attn_kernel<<<NBLK, TPB, smem>>>(q, k, v, tab, out);
}